// round 1
// baseline (speedup 1.0000x reference)
#include <cuda_runtime.h>
#include <math.h>

#define Bn   2
#define Ln   1024
#define Dn   1024
#define Hn   16
#define HDn  64
#define HIDn 4096
#define Mn   (Bn*Ln)        /* 2048 rows */
#define EPSc 1e-6f
#define SCALEc 0.125f       /* 64^-0.5 */

// ---------------- scratch (device globals; no runtime allocation) ----------
__device__ float g_hr[Mn*Dn],  g_hi[Mn*Dn];
__device__ float g_qr[Mn*Dn],  g_qi[Mn*Dn];
__device__ float g_kr[Mn*Dn],  g_ki[Mn*Dn];
__device__ float g_vr[Mn*Dn],  g_vi[Mn*Dn];
__device__ float g_s [Bn*Hn*Ln*Ln];          /* 128 MB scores/attn */
__device__ float g_aor[Mn*Dn], g_aoi[Mn*Dn];
__device__ float g_ar[Mn*Dn],  g_ai[Mn*Dn];
__device__ float g_fr[Mn*HIDn], g_fi[Mn*HIDn];

// ---------------- complex layernorm ----------------------------------------
__global__ void cln_kernel(const float* __restrict__ xr, const float* __restrict__ xi,
                           const float* __restrict__ gr, const float* __restrict__ gi,
                           const float* __restrict__ bre, const float* __restrict__ bim,
                           float* __restrict__ outr, float* __restrict__ outi)
{
    int row = blockIdx.x;
    const float* pr = xr + (size_t)row * Dn;
    const float* pi = xi + (size_t)row * Dn;
    __shared__ float s1[256], s2[256];
    int tid = threadIdx.x;
    float sr = 0.f, si = 0.f;
    for (int j = tid; j < Dn; j += 256) { sr += pr[j]; si += pi[j]; }
    s1[tid] = sr; s2[tid] = si;
    __syncthreads();
    for (int o = 128; o > 0; o >>= 1) {
        if (tid < o) { s1[tid] += s1[tid+o]; s2[tid] += s2[tid+o]; }
        __syncthreads();
    }
    float mr = s1[0] * (1.f/Dn), mi = s2[0] * (1.f/Dn);
    __syncthreads();
    float v = 0.f;
    for (int j = tid; j < Dn; j += 256) {
        float cr = pr[j] - mr, ci = pi[j] - mi;
        v += cr*cr + ci*ci;
    }
    s1[tid] = v;
    __syncthreads();
    for (int o = 128; o > 0; o >>= 1) {
        if (tid < o) s1[tid] += s1[tid+o];
        __syncthreads();
    }
    float inv = rsqrtf(s1[0] * (1.f/Dn) + EPSc);
    for (int j = tid; j < Dn; j += 256) {
        float nr = (pr[j]-mr)*inv, ni = (pi[j]-mi)*inv;
        outr[(size_t)row*Dn + j] = nr*gr[j] - ni*gi[j] + bre[j];
        outi[(size_t)row*Dn + j] = nr*gi[j] + ni*gr[j] + bim[j];
    }
}

// ---------------- complex GEMM: C = A @ B^T (A:[M,K], B:[N,K] row-major) ----
// optional bias[N] and residual[M,N] in epilogue
__global__ __launch_bounds__(256, 2)
void cgemm_nt(const float* __restrict__ Ar, const float* __restrict__ Ai,
              const float* __restrict__ Br, const float* __restrict__ Bi,
              float* __restrict__ Cr, float* __restrict__ Ci,
              int M, int N, int K,
              const float* __restrict__ biasr, const float* __restrict__ biasi,
              const float* __restrict__ resr,  const float* __restrict__ resi)
{
    __shared__ float Asr[16][132], Asi[16][132];
    __shared__ float Bsr[16][68],  Bsi[16][68];
    const int tid = threadIdx.x;
    const int bm = blockIdx.y * 128, bn = blockIdx.x * 64;
    const int tx = tid & 15, ty = tid >> 4;
    const int r0 = ty * 8, c0 = tx * 4;
    const int lm = tid >> 2, lk = (tid & 3) * 4;

    float cr[8][4], ci[8][4];
#pragma unroll
    for (int i = 0; i < 8; i++)
#pragma unroll
        for (int j = 0; j < 4; j++) { cr[i][j] = 0.f; ci[i][j] = 0.f; }

    for (int k0 = 0; k0 < K; k0 += 16) {
#pragma unroll
        for (int p = 0; p < 2; p++) {
            int row = bm + p*64 + lm;
            float4 a4r = *(const float4*)(Ar + (size_t)row * K + k0 + lk);
            float4 a4i = *(const float4*)(Ai + (size_t)row * K + k0 + lk);
            int col = p*64 + lm;
            Asr[lk+0][col] = a4r.x; Asr[lk+1][col] = a4r.y;
            Asr[lk+2][col] = a4r.z; Asr[lk+3][col] = a4r.w;
            Asi[lk+0][col] = a4i.x; Asi[lk+1][col] = a4i.y;
            Asi[lk+2][col] = a4i.z; Asi[lk+3][col] = a4i.w;
        }
        {
            int row = bn + lm;
            float4 b4r = *(const float4*)(Br + (size_t)row * K + k0 + lk);
            float4 b4i = *(const float4*)(Bi + (size_t)row * K + k0 + lk);
            Bsr[lk+0][lm] = b4r.x; Bsr[lk+1][lm] = b4r.y;
            Bsr[lk+2][lm] = b4r.z; Bsr[lk+3][lm] = b4r.w;
            Bsi[lk+0][lm] = b4i.x; Bsi[lk+1][lm] = b4i.y;
            Bsi[lk+2][lm] = b4i.z; Bsi[lk+3][lm] = b4i.w;
        }
        __syncthreads();
#pragma unroll
        for (int kk = 0; kk < 16; kk++) {
            float ar[8], ai[8], br[4], bi[4];
            *(float4*)&ar[0] = *(const float4*)&Asr[kk][r0];
            *(float4*)&ar[4] = *(const float4*)&Asr[kk][r0+4];
            *(float4*)&ai[0] = *(const float4*)&Asi[kk][r0];
            *(float4*)&ai[4] = *(const float4*)&Asi[kk][r0+4];
            *(float4*)&br[0] = *(const float4*)&Bsr[kk][c0];
            *(float4*)&bi[0] = *(const float4*)&Bsi[kk][c0];
#pragma unroll
            for (int i = 0; i < 8; i++)
#pragma unroll
                for (int j = 0; j < 4; j++) {
                    cr[i][j] = fmaf(ar[i],  br[j], cr[i][j]);
                    cr[i][j] = fmaf(-ai[i], bi[j], cr[i][j]);
                    ci[i][j] = fmaf(ar[i],  bi[j], ci[i][j]);
                    ci[i][j] = fmaf(ai[i],  br[j], ci[i][j]);
                }
        }
        __syncthreads();
    }
#pragma unroll
    for (int i = 0; i < 8; i++) {
        int row = bm + r0 + i;
#pragma unroll
        for (int j = 0; j < 4; j++) {
            int col = bn + c0 + j;
            float vr = cr[i][j], vi = ci[i][j];
            if (biasr) { vr += biasr[col]; vi += biasi[col]; }
            if (resr)  { vr += resr[(size_t)row*N + col]; vi += resi[(size_t)row*N + col]; }
            Cr[(size_t)row*N + col] = vr;
            Ci[(size_t)row*N + col] = vi;
        }
    }
}

// ---------------- RoPE (in place, per (b,l,h, pair j<32)) ------------------
__global__ void rope_kernel(float* __restrict__ xr, float* __restrict__ xi)
{
    int idx = blockIdx.x * blockDim.x + threadIdx.x;   // Bn*Ln*Hn*32 threads
    int j = idx & 31;
    int t = idx >> 5;
    int h = t & (Hn-1); t >>= 4;
    int l = t & (Ln-1);
    int b = t >> 10;
    size_t base = ((size_t)(b*Ln + l)) * Dn + h * HDn;
    double invf = exp(-((double)(2*j) / (double)HDn) * 9.210340371976184); // ln(1e4)
    double th = (double)l * invf;
    double sd, cd;
    sincos(th, &sd, &cd);
    float c = (float)cd, s = (float)sd;
    float a0 = xr[base+j], a1 = xr[base+j+32];
    xr[base+j]    = a0*c - a1*s;
    xr[base+j+32] = a1*c + a0*s;
    float b0 = xi[base+j], b1 = xi[base+j+32];
    xi[base+j]    = b0*c - b1*s;
    xi[base+j+32] = b1*c + b0*s;
}

// ---------------- scores = (Qr Kr^T + Qi Ki^T) * SCALE, causal-block-skip ---
__global__ __launch_bounds__(256, 2)
void scores_kernel(const float* __restrict__ Q_r, const float* __restrict__ Q_i,
                   const float* __restrict__ K_r, const float* __restrict__ K_i,
                   float* __restrict__ S)
{
    int bh = blockIdx.z;
    int b = bh >> 4, h = bh & 15;
    int bm = blockIdx.y * 128, bn = blockIdx.x * 64;
    if (bn > bm + 127) return;                      // fully masked block
    const size_t off = (size_t)b * Ln * Dn + (size_t)h * HDn;
    const float* Ar = Q_r + off; const float* Ai = Q_i + off;
    const float* Br = K_r + off; const float* Bi = K_i + off;
    __shared__ float Asr[16][132], Asi[16][132], Bsr[16][68], Bsi[16][68];
    const int tid = threadIdx.x;
    const int tx = tid & 15, ty = tid >> 4;
    const int r0 = ty * 8, c0 = tx * 4;
    const int lm = tid >> 2, lk = (tid & 3) * 4;
    float acc[8][4];
#pragma unroll
    for (int i = 0; i < 8; i++)
#pragma unroll
        for (int j = 0; j < 4; j++) acc[i][j] = 0.f;

#pragma unroll
    for (int k0 = 0; k0 < HDn; k0 += 16) {
#pragma unroll
        for (int p = 0; p < 2; p++) {
            int row = bm + p*64 + lm;
            float4 a4r = *(const float4*)(Ar + (size_t)row * Dn + k0 + lk);
            float4 a4i = *(const float4*)(Ai + (size_t)row * Dn + k0 + lk);
            int col = p*64 + lm;
            Asr[lk+0][col] = a4r.x; Asr[lk+1][col] = a4r.y;
            Asr[lk+2][col] = a4r.z; Asr[lk+3][col] = a4r.w;
            Asi[lk+0][col] = a4i.x; Asi[lk+1][col] = a4i.y;
            Asi[lk+2][col] = a4i.z; Asi[lk+3][col] = a4i.w;
        }
        {
            int row = bn + lm;
            float4 b4r = *(const float4*)(Br + (size_t)row * Dn + k0 + lk);
            float4 b4i = *(const float4*)(Bi + (size_t)row * Dn + k0 + lk);
            Bsr[lk+0][lm] = b4r.x; Bsr[lk+1][lm] = b4r.y;
            Bsr[lk+2][lm] = b4r.z; Bsr[lk+3][lm] = b4r.w;
            Bsi[lk+0][lm] = b4i.x; Bsi[lk+1][lm] = b4i.y;
            Bsi[lk+2][lm] = b4i.z; Bsi[lk+3][lm] = b4i.w;
        }
        __syncthreads();
#pragma unroll
        for (int kk = 0; kk < 16; kk++) {
            float ar[8], ai[8], br[4], bi[4];
            *(float4*)&ar[0] = *(const float4*)&Asr[kk][r0];
            *(float4*)&ar[4] = *(const float4*)&Asr[kk][r0+4];
            *(float4*)&ai[0] = *(const float4*)&Asi[kk][r0];
            *(float4*)&ai[4] = *(const float4*)&Asi[kk][r0+4];
            *(float4*)&br[0] = *(const float4*)&Bsr[kk][c0];
            *(float4*)&bi[0] = *(const float4*)&Bsi[kk][c0];
#pragma unroll
            for (int i = 0; i < 8; i++)
#pragma unroll
                for (int j = 0; j < 4; j++) {
                    acc[i][j] = fmaf(ar[i], br[j], acc[i][j]);
                    acc[i][j] = fmaf(ai[i], bi[j], acc[i][j]);
                }
        }
        __syncthreads();
    }
#pragma unroll
    for (int i = 0; i < 8; i++) {
        int row = bm + r0 + i;
#pragma unroll
        for (int j = 0; j < 4; j++) {
            int col = bn + c0 + j;
            S[((size_t)bh * Ln + row) * Ln + col] = acc[i][j] * SCALEc;
        }
    }
}

// ---------------- causal softmax (in place), zeros above diagonal -----------
__global__ void softmax_kernel(float* __restrict__ S)
{
    int row = blockIdx.x;                 // 0 .. B*H*L-1
    int l = row & (Ln - 1);
    float* p = S + (size_t)row * Ln;
    __shared__ float red[256];
    int tid = threadIdx.x;
    float m = -1e30f;
    for (int j = tid; j <= l; j += 256) m = fmaxf(m, p[j]);
    red[tid] = m; __syncthreads();
    for (int o = 128; o > 0; o >>= 1) {
        if (tid < o) red[tid] = fmaxf(red[tid], red[tid+o]);
        __syncthreads();
    }
    m = red[0]; __syncthreads();
    float s = 0.f;
    for (int j = tid; j <= l; j += 256) s += expf(p[j] - m);
    red[tid] = s; __syncthreads();
    for (int o = 128; o > 0; o >>= 1) {
        if (tid < o) red[tid] += red[tid+o];
        __syncthreads();
    }
    float inv = 1.f / red[0];
    for (int j = tid; j < Ln; j += 256)
        p[j] = (j <= l) ? expf(p[j] - m) * inv : 0.f;
}

// ---------------- out = attn @ V (both r and i), causal k-loop truncation ---
__global__ __launch_bounds__(256, 2)
void av_kernel(const float* __restrict__ S,
               const float* __restrict__ V_r, const float* __restrict__ V_i,
               float* __restrict__ Or, float* __restrict__ Oi)
{
    int bh = blockIdx.z;
    int b = bh >> 4, h = bh & 15;
    int bm = blockIdx.y * 128;
    const float* P = S + (size_t)bh * Ln * Ln;
    const size_t voff = (size_t)b * Ln * Dn + (size_t)h * HDn;
    __shared__ float As[16][132], Bsr[16][68], Bsi[16][68];
    const int tid = threadIdx.x;
    const int tx = tid & 15, ty = tid >> 4;
    const int r0 = ty * 8, c0 = tx * 4;
    const int lm = tid >> 2, lk = (tid & 3) * 4;
    const int vrow = tid >> 4, vc4 = (tid & 15) * 4;
    float cr[8][4], ci[8][4];
#pragma unroll
    for (int i = 0; i < 8; i++)
#pragma unroll
        for (int j = 0; j < 4; j++) { cr[i][j] = 0.f; ci[i][j] = 0.f; }

    int kmax = bm + 128;                   // rows in this block see m <= bm+127
    for (int k0 = 0; k0 < kmax; k0 += 16) {
#pragma unroll
        for (int p = 0; p < 2; p++) {
            int row = bm + p*64 + lm;
            float4 a4 = *(const float4*)(P + (size_t)row * Ln + k0 + lk);
            int col = p*64 + lm;
            As[lk+0][col] = a4.x; As[lk+1][col] = a4.y;
            As[lk+2][col] = a4.z; As[lk+3][col] = a4.w;
        }
        {
            float4 v4r = *(const float4*)(V_r + voff + (size_t)(k0 + vrow) * Dn + vc4);
            float4 v4i = *(const float4*)(V_i + voff + (size_t)(k0 + vrow) * Dn + vc4);
            Bsr[vrow][vc4+0] = v4r.x; Bsr[vrow][vc4+1] = v4r.y;
            Bsr[vrow][vc4+2] = v4r.z; Bsr[vrow][vc4+3] = v4r.w;
            Bsi[vrow][vc4+0] = v4i.x; Bsi[vrow][vc4+1] = v4i.y;
            Bsi[vrow][vc4+2] = v4i.z; Bsi[vrow][vc4+3] = v4i.w;
        }
        __syncthreads();
#pragma unroll
        for (int kk = 0; kk < 16; kk++) {
            float a[8], br[4], bi[4];
            *(float4*)&a[0] = *(const float4*)&As[kk][r0];
            *(float4*)&a[4] = *(const float4*)&As[kk][r0+4];
            *(float4*)&br[0] = *(const float4*)&Bsr[kk][c0];
            *(float4*)&bi[0] = *(const float4*)&Bsi[kk][c0];
#pragma unroll
            for (int i = 0; i < 8; i++)
#pragma unroll
                for (int j = 0; j < 4; j++) {
                    cr[i][j] = fmaf(a[i], br[j], cr[i][j]);
                    ci[i][j] = fmaf(a[i], bi[j], ci[i][j]);
                }
        }
        __syncthreads();
    }
#pragma unroll
    for (int i = 0; i < 8; i++) {
        int row = bm + r0 + i;
#pragma unroll
        for (int j = 0; j < 4; j++) {
            Or[voff + (size_t)row * Dn + c0 + j] = cr[i][j];
            Oi[voff + (size_t)row * Dn + c0 + j] = ci[i][j];
        }
    }
}

// ---------------- ModReLU ---------------------------------------------------
__global__ void modrelu_kernel(float* __restrict__ fr, float* __restrict__ fi,
                               const float* __restrict__ mb)
{
    size_t idx = (size_t)blockIdx.x * blockDim.x + threadIdx.x;
    int col = (int)(idx & (HIDn - 1));
    float r = fr[idx], i = fi[idx];
    float mag = sqrtf(r*r + i*i);
    float safe = mag > 0.f ? mag : 1.f;
    float act = fmaxf(mag + mb[col], 0.f);
    float fac = act / safe;
    fr[idx] = r * fac;
    fi[idx] = i * fac;
}

// ---------------- launch ----------------------------------------------------
extern "C" void kernel_launch(void* const* d_in, const int* in_sizes, int n_in,
                              void* d_out, int out_size)
{
    const float* x_r   = (const float*)d_in[0];
    const float* x_i   = (const float*)d_in[1];
    const float* Wq_r  = (const float*)d_in[2];
    const float* Wq_i  = (const float*)d_in[3];
    const float* Wk_r  = (const float*)d_in[4];
    const float* Wk_i  = (const float*)d_in[5];
    const float* Wv_r  = (const float*)d_in[6];
    const float* Wv_i  = (const float*)d_in[7];
    const float* Wo_r  = (const float*)d_in[8];
    const float* Wo_i  = (const float*)d_in[9];
    const float* bo_r  = (const float*)d_in[10];
    const float* bo_i  = (const float*)d_in[11];
    const float* ln1_gr = (const float*)d_in[12];
    const float* ln1_gi = (const float*)d_in[13];
    const float* ln1_br = (const float*)d_in[14];
    const float* ln1_bi = (const float*)d_in[15];
    const float* ln2_gr = (const float*)d_in[16];
    const float* ln2_gi = (const float*)d_in[17];
    const float* ln2_br = (const float*)d_in[18];
    const float* ln2_bi = (const float*)d_in[19];
    const float* W1_r  = (const float*)d_in[20];
    const float* W1_i  = (const float*)d_in[21];
    const float* b1_r  = (const float*)d_in[22];
    const float* b1_i  = (const float*)d_in[23];
    const float* W2_r  = (const float*)d_in[24];
    const float* W2_i  = (const float*)d_in[25];
    const float* b2_r  = (const float*)d_in[26];
    const float* b2_i  = (const float*)d_in[27];
    const float* mod_b = (const float*)d_in[28];
    float* out = (float*)d_out;

    float *hr, *hi, *qr, *qi, *kr, *ki, *vr, *vi, *sb, *aor, *aoi, *ar, *ai, *fr, *fi;
    cudaGetSymbolAddress((void**)&hr,  g_hr);
    cudaGetSymbolAddress((void**)&hi,  g_hi);
    cudaGetSymbolAddress((void**)&qr,  g_qr);
    cudaGetSymbolAddress((void**)&qi,  g_qi);
    cudaGetSymbolAddress((void**)&kr,  g_kr);
    cudaGetSymbolAddress((void**)&ki,  g_ki);
    cudaGetSymbolAddress((void**)&vr,  g_vr);
    cudaGetSymbolAddress((void**)&vi,  g_vi);
    cudaGetSymbolAddress((void**)&sb,  g_s);
    cudaGetSymbolAddress((void**)&aor, g_aor);
    cudaGetSymbolAddress((void**)&aoi, g_aoi);
    cudaGetSymbolAddress((void**)&ar,  g_ar);
    cudaGetSymbolAddress((void**)&ai,  g_ai);
    cudaGetSymbolAddress((void**)&fr,  g_fr);
    cudaGetSymbolAddress((void**)&fi,  g_fi);

    // 1. LN1
    cln_kernel<<<Mn, 256>>>(x_r, x_i, ln1_gr, ln1_gi, ln1_br, ln1_bi, hr, hi);

    // 2. QKV projections (complex, no bias)
    dim3 gproj(Dn/64, Mn/128);
    cgemm_nt<<<gproj, 256>>>(hr, hi, Wq_r, Wq_i, qr, qi, Mn, Dn, Dn, nullptr, nullptr, nullptr, nullptr);
    cgemm_nt<<<gproj, 256>>>(hr, hi, Wk_r, Wk_i, kr, ki, Mn, Dn, Dn, nullptr, nullptr, nullptr, nullptr);
    cgemm_nt<<<gproj, 256>>>(hr, hi, Wv_r, Wv_i, vr, vi, Mn, Dn, Dn, nullptr, nullptr, nullptr, nullptr);

    // 3. RoPE on Q and K
    rope_kernel<<<(Bn*Ln*Hn*32)/256, 256>>>(qr, qi);
    rope_kernel<<<(Bn*Ln*Hn*32)/256, 256>>>(kr, ki);

    // 4. scores + softmax + attn@V
    scores_kernel<<<dim3(Ln/64, Ln/128, Bn*Hn), 256>>>(qr, qi, kr, ki, sb);
    softmax_kernel<<<Bn*Hn*Ln, 256>>>(sb);
    av_kernel<<<dim3(1, Ln/128, Bn*Hn), 256>>>(sb, vr, vi, aor, aoi);

    // 5. out projection + bias + residual(x)
    cgemm_nt<<<gproj, 256>>>(aor, aoi, Wo_r, Wo_i, ar, ai, Mn, Dn, Dn, bo_r, bo_i, x_r, x_i);

    // 6. LN2
    cln_kernel<<<Mn, 256>>>(ar, ai, ln2_gr, ln2_gi, ln2_br, ln2_bi, hr, hi);

    // 7. FC1 + bias
    cgemm_nt<<<dim3(HIDn/64, Mn/128), 256>>>(hr, hi, W1_r, W1_i, fr, fi, Mn, HIDn, Dn, b1_r, b1_i, nullptr, nullptr);

    // 8. ModReLU
    modrelu_kernel<<<(Mn*(size_t)HIDn)/256, 256>>>(fr, fi, mod_b);

    // 9. FC2 + bias + residual(ar/ai) -> output (real half, imag half)
    cgemm_nt<<<gproj, 256>>>(fr, fi, W2_r, W2_i, out, out + (size_t)Mn*Dn, Mn, Dn, HIDn, b2_r, b2_i, ar, ai);
}